// round 16
// baseline (speedup 1.0000x reference)
#include <cuda_runtime.h>
#include <cuda_fp16.h>
#include <math.h>
#include <stdint.h>

#define NV 24576
#define NC 98304
#define NE 294912
#define NL 49152
#define INV_M (1.0f/12582912.0f)
#define CSR_W 40

// ---------------- workspace layout (floats) ----------------
static constexpr size_t O_VARS   = 0;
static constexpr size_t O_CLS    = O_VARS  + (size_t)NV*128;
static constexpr size_t O_CQ     = O_CLS   + (size_t)NC*128;
static constexpr size_t O_VQ     = O_CQ    + (size_t)NC*128;
static constexpr size_t O_LOSS   = O_VQ    + (size_t)NV*128;
static constexpr size_t O_CDATA  = O_LOSS  + (size_t)NC*128;   // NC x 256
static constexpr size_t O_VOUT   = O_CDATA + (size_t)NC*256;   // NV x 128
static constexpr size_t O_SP     = O_VOUT  + (size_t)NV*128;   // NL x 128
static constexpr size_t O_DEGW   = O_SP    + (size_t)NL*128;   // NL
static constexpr size_t O_VDEGW  = O_DEGW  + NL;               // NV
static constexpr size_t O_STATC  = O_VDEGW + NV;               // 512
static constexpr size_t O_STATV  = O_STATC + 512;              // 512
static constexpr size_t O_WT     = O_STATV + 512;              // fp16 weights
static constexpr size_t O_H16    = O_WT + 240000;              // fp16 area base

// half offsets within H16 area
static constexpr size_t H_CLSCAT  = 0;                              // NC x 136
static constexpr size_t H_VARSCAT = H_CLSCAT  + (size_t)NC*136;     // NV x 136
static constexpr size_t H_CMIN    = H_VARSCAT + (size_t)NV*136;     // NC x 384
static constexpr size_t H_UNIT    = H_CMIN    + (size_t)NC*384;     // NV x 512
static constexpr size_t H_A       = H_UNIT    + (size_t)NV*512;     // NC x 256
static constexpr size_t H_B       = H_A       + (size_t)NC*256;     // NV x 256
static constexpr size_t H_END     = H_B       + (size_t)NV*256;
static constexpr size_t WS_TOTAL  = O_H16 + (H_END + 1)/2 + 64;

static constexpr size_t OW_vq0 = 0;
static constexpr size_t OW_vq1 = 17408;
static constexpr size_t OW_cq0 = 33792;
static constexpr size_t OW_cq1 = 51200;
static constexpr size_t OW_cm0 = 67584;
static constexpr size_t OW_cm1 = 165888;
static constexpr size_t OW_ug0 = 231424;
static constexpr size_t OW_ug1 = 362496;
static constexpr size_t OW_ug2 = 428032;
static constexpr size_t OW_co0 = 460800;
static constexpr int    OW_END = 477184;

__device__ float g_ws[WS_TOTAL];
__device__ int   g_deg[NL];
__device__ int   g_csr[(size_t)NL * CSR_W];

// ---------------- PTX helpers ----------------
__device__ __forceinline__ uint32_t smem_u32(const void* p){
    uint32_t a;
    asm("{ .reg .u64 t; cvta.to.shared.u64 t, %1; cvt.u32.u64 %0, t; }" : "=r"(a) : "l"(p));
    return a;
}
__device__ __forceinline__ void ldsm4(uint32_t* r, uint32_t addr){
    asm volatile("ldmatrix.sync.aligned.m8n8.x4.shared.b16 {%0,%1,%2,%3}, [%4];"
        : "=r"(r[0]), "=r"(r[1]), "=r"(r[2]), "=r"(r[3]) : "r"(addr));
}
__device__ __forceinline__ void mma_f16(float* c, const uint32_t* a, const uint32_t* b){
    asm volatile("mma.sync.aligned.m16n8k16.row.col.f32.f16.f16.f32 "
        "{%0,%1,%2,%3}, {%4,%5,%6,%7}, {%8,%9}, {%0,%1,%2,%3};"
        : "+f"(c[0]), "+f"(c[1]), "+f"(c[2]), "+f"(c[3])
        : "r"(a[0]), "r"(a[1]), "r"(a[2]), "r"(a[3]), "r"(b[0]), "r"(b[1]));
}
__device__ __forceinline__ void cp16(uint32_t dst, const void* src, bool pred){
    int sz = pred ? 16 : 0;
    asm volatile("cp.async.cg.shared.global [%0], [%1], 16, %2;"
                 :: "r"(dst), "l"(src), "r"(sz));
}
__device__ __forceinline__ void cp16ca(uint32_t dst, const void* src, bool pred){
    int sz = pred ? 16 : 0;
    asm volatile("cp.async.ca.shared.global [%0], [%1], 16, %2;"
                 :: "r"(dst), "l"(src), "r"(sz));
}
#define CP_COMMIT() asm volatile("cp.async.commit_group;" ::: "memory")
#define CP_WAIT2()  asm volatile("cp.async.wait_group 2;" ::: "memory")
#define CP_WAIT1()  asm volatile("cp.async.wait_group 1;" ::: "memory")

__device__ __forceinline__ float sigm(float x){ return 1.f/(1.f+expf(-x)); }
__device__ __forceinline__ float softplusf(float x){ return fmaxf(x,0.f)+log1pf(expf(-fabsf(x))); }
__device__ __forceinline__ float fsigm(float x){ return __fdividef(1.f, 1.f+__expf(-x)); }
__device__ __forceinline__ float fsoftplus(float x){ return fmaxf(x,0.f)+__logf(1.f+__expf(-fabsf(x))); }

__device__ __forceinline__ uint2 pack_h4(float a, float b, float c, float d){
    __half2 h0 = __floats2half2_rn(a, b);
    __half2 h1 = __floats2half2_rn(c, d);
    uint2 r;
    r.x = *reinterpret_cast<uint32_t*>(&h0);
    r.y = *reinterpret_cast<uint32_t*>(&h1);
    return r;
}

// ---------------- unified fp16 A16 GEMM, MT x 128 tile, early-prefetch depth-3 ----------------
// MT in {64,128}. 256 thr, 2 CTAs/SM. Dual weight sets selected by bm >= rowSplit.
template<int MT, int STATS, int CH, int SPE>
__global__ void __launch_bounds__(256, 2)
k_mma64(const __half* __restrict__ A16,
        const __half* __restrict__ Bg1, const __half* __restrict__ Bg2,
        const float* __restrict__ bias1, const float* __restrict__ bias2,
        void* __restrict__ Cv, int KP, int Ntot, int relu, int rowSplit,
        float* __restrict__ statp, float* __restrict__ spbuf)
{
    extern __shared__ __align__(16) char smem[];
    const uint32_t sbase = smem_u32(smem);
    const int t = threadIdx.x;
    const int lane = t & 31, wid = t >> 5;
    constexpr int NT   = (MT == 128) ? 8 : 4;      // n-subtiles per warp
    constexpr int CPW  = (MT == 128) ? 64 : 32;    // cols per warp
    const int warp_m = (MT == 128) ? (wid & 3) : (wid & 1);
    const int warp_n = (MT == 128) ? (wid >> 2) : (wid >> 1);
    const int bm = blockIdx.y * MT, bn = blockIdx.x * 128;
    const bool part2 = (bm >= rowSplit);
    const __half* Bg  = part2 ? Bg2 : Bg1;
    const float* bias = part2 ? bias2 : bias1;

    constexpr int LDH = 40;
    constexpr int APLANE = MT*LDH*2;
    constexpr int BPLANE = 10240;
    constexpr int A0 = 0, B0 = 4*APLANE;

    float acc[2][NT][4];
    #pragma unroll
    for (int i=0;i<2;i++)
        #pragma unroll
        for(int j=0;j<NT;j++)
            #pragma unroll
            for(int q=0;q<4;q++) acc[i][j][q]=0.f;

    const int nch = (KP + 31) >> 5;

    auto cpAB = [&](int c){
        const int k0 = c << 5;
        const uint32_t ab = sbase + A0 + (uint32_t)(c & 3)*APLANE;
        const uint32_t bb = sbase + B0 + (uint32_t)(c & 3)*BPLANE;
        #pragma unroll
        for (int i = 0; i < MT/64; i++) {
            int idx = t + i*256;
            int row = idx >> 2, q = idx & 3;
            int gk = k0 + q*8;
            bool ok = (gk + 8 <= KP);
            size_t aoff = ok ? ((size_t)(bm+row)*KP + gk) : 0;
            cp16(ab + (uint32_t)(row*LDH + q*8)*2, A16 + aoff, ok);
        }
        #pragma unroll
        for (int i = 0; i < 2; i++) {
            int idx = t + i*256;
            int row = idx >> 2, q = idx & 3;
            int gk = k0 + q*8;
            bool ok = (gk + 8 <= KP);
            size_t boff = ok ? ((size_t)(bn+row)*KP + gk) : 0;
            cp16ca(bb + (uint32_t)(row*LDH + q*8)*2, Bg + boff, ok);
        }
    };
    auto compute = [&](int c){
        const uint32_t sa = sbase + A0 + (uint32_t)(c & 3)*APLANE;
        const uint32_t sb = sbase + B0 + (uint32_t)(c & 3)*BPLANE;
        const int grp = lane >> 3, r = lane & 7;
        #pragma unroll
        for (int ks = 0; ks < 32; ks += 16) {
            uint32_t aH[2][4], bX[NT][2];
            #pragma unroll
            for (int mt = 0; mt < 2; mt++) {
                int arow = warp_m*32 + mt*16 + (grp & 1)*8 + r;
                int acol = ks + (grp >> 1)*8;
                ldsm4(aH[mt], sa + (uint32_t)(arow*LDH + acol)*2);
            }
            #pragma unroll
            for (int p = 0; p < NT/2; p++) {
                int brow = warp_n*CPW + p*16 + (grp >> 1)*8 + r;
                int bcol = ks + (grp & 1)*8;
                uint32_t tmp[4];
                ldsm4(tmp, sb + (uint32_t)(brow*LDH + bcol)*2);
                bX[2*p][0]=tmp[0]; bX[2*p][1]=tmp[1]; bX[2*p+1][0]=tmp[2]; bX[2*p+1][1]=tmp[3];
            }
            #pragma unroll
            for (int mt = 0; mt < 2; mt++)
                #pragma unroll
                for (int nt = 0; nt < NT; nt++)
                    mma_f16(acc[mt][nt], aH[mt], bX[nt]);
        }
    };

    cpAB(0);
    CP_COMMIT();
    if (nch > 1) cpAB(1);
    CP_COMMIT();
    if (nch > 2) cpAB(2);
    CP_COMMIT();

    for (int c = 0; c < nch; c++) {
        CP_WAIT2();
        __syncthreads();
        if (c+3 < nch) cpAB(c+3);
        CP_COMMIT();
        compute(c);
    }

    // ---- C store (+SPE) ----
    #pragma unroll
    for (int mt = 0; mt < 2; mt++) {
        int row0 = bm + warp_m*32 + mt*16 + (lane >> 2);
        #pragma unroll
        for (int nt = 0; nt < NT; nt++) {
            int col = bn + warp_n*CPW + nt*8 + (lane & 3)*2;
            float2 bv = *reinterpret_cast<const float2*>(&bias[col - bn]);
            float v0 = acc[mt][nt][0] + bv.x, v1 = acc[mt][nt][1] + bv.y;
            float v2 = acc[mt][nt][2] + bv.x, v3 = acc[mt][nt][3] + bv.y;
            if (relu) { v0=fmaxf(v0,0.f); v1=fmaxf(v1,0.f); v2=fmaxf(v2,0.f); v3=fmaxf(v3,0.f); }
            if (CH) {
                __half* C16 = reinterpret_cast<__half*>(Cv);
                __half2 h01 = __floats2half2_rn(v0, v1);
                __half2 h23 = __floats2half2_rn(v2, v3);
                *reinterpret_cast<__half2*>(&C16[(size_t)row0*Ntot + col])     = h01;
                *reinterpret_cast<__half2*>(&C16[(size_t)(row0+8)*Ntot + col]) = h23;
            } else {
                float* C = reinterpret_cast<float*>(Cv);
                *reinterpret_cast<float2*>(&C[(size_t)row0*Ntot + col])     = make_float2(v0,v1);
                *reinterpret_cast<float2*>(&C[(size_t)(row0+8)*Ntot + col]) = make_float2(v2,v3);
            }
            if (SPE) {
                if (part2) {
                    int rv = row0 - rowSplit;
                    *reinterpret_cast<float2*>(&spbuf[(size_t)rv*128 + col]) =
                        make_float2(fsoftplus(v0), fsoftplus(v1));
                    *reinterpret_cast<float2*>(&spbuf[(size_t)(rv+NV)*128 + col]) =
                        make_float2(fsoftplus(-v0), fsoftplus(-v1));
                    *reinterpret_cast<float2*>(&spbuf[(size_t)(rv+8)*128 + col]) =
                        make_float2(fsoftplus(v2), fsoftplus(v3));
                    *reinterpret_cast<float2*>(&spbuf[(size_t)(rv+8+NV)*128 + col]) =
                        make_float2(fsoftplus(-v2), fsoftplus(-v3));
                }
            }
        }
    }

    if (STATS) {
        bool active = (STATS == 2) || (bn >= 128);
        if (active) {
            __syncthreads();
            float* red = reinterpret_cast<float*>(smem);
            if (t < 256) red[t] = 0.f;
            __syncthreads();
            #pragma unroll
            for (int nt = 0; nt < NT; nt++) {
                int c0 = warp_n*CPW + nt*8 + (lane & 3)*2;
                float b0 = __ldg(&bias[c0]), b1 = __ldg(&bias[c0 + 1]);
                float s0=0.f, s1=0.f, q0=0.f, q1=0.f;
                #pragma unroll
                for (int mt = 0; mt < 2; mt++) {
                    float v0 = acc[mt][nt][0] + b0, v1 = acc[mt][nt][1] + b1;
                    float v2 = acc[mt][nt][2] + b0, v3 = acc[mt][nt][3] + b1;
                    s0 += v0 + v2; s1 += v1 + v3;
                    q0 += v0*v0 + v2*v2; q1 += v1*v1 + v3*v3;
                }
                #pragma unroll
                for (int o = 4; o < 32; o <<= 1) {
                    s0 += __shfl_xor_sync(0xffffffffu, s0, o);
                    s1 += __shfl_xor_sync(0xffffffffu, s1, o);
                    q0 += __shfl_xor_sync(0xffffffffu, q0, o);
                    q1 += __shfl_xor_sync(0xffffffffu, q1, o);
                }
                if (lane < 4) {
                    atomicAdd(&red[c0],        s0);
                    atomicAdd(&red[c0+1],      s1);
                    atomicAdd(&red[128+c0],    q0);
                    atomicAdd(&red[128+c0+1],  q1);
                }
            }
            __syncthreads();
            if (t < 128) {
                atomicAdd(&statp[t],       red[t]);
                atomicAdd(&statp[128 + t], red[128 + t]);
            }
        }
    }
}

// ---------------- co0: pn-apply loader (+fp16 state writes) + logits ----------------
static constexpr int CO_SMEM = 51200;

__global__ void __launch_bounds__(512, 1)
k_co0(const float* __restrict__ cdata, float* __restrict__ cls,
      const float* __restrict__ statc,
      const __half* __restrict__ Bg, const float* __restrict__ bias,
      float* __restrict__ out, int round,
      const float* __restrict__ w1, const float* __restrict__ b1,
      __half* __restrict__ clscat, __half* __restrict__ cmin16)
{
    extern __shared__ __align__(16) char smem[];
    const uint32_t sbase = smem_u32(smem);
    const int t = threadIdx.x;
    const int lane = t & 31, wid = t >> 5;
    const int warp_m = wid & 3, warp_n = wid >> 2;
    const int bm = blockIdx.y * 128;

    constexpr int LDH = 40, PLANE = 10240, A0 = 0, B0 = 20480;
    constexpr int K = 128, nch = 4;

    float acc[2][4][4];
    #pragma unroll
    for (int i=0;i<2;i++)
        #pragma unroll
        for(int j=0;j<4;j++)
            #pragma unroll
            for(int q=0;q<4;q++) acc[i][j][q]=0.f;

    float4 aReg[2];
    const float scale = statc[384];

    auto loadA = [&](int c){
        const int k0 = c << 5;
        #pragma unroll
        for (int i = 0; i < 2; i++) {
            int idx = t + i*512;
            int row = idx >> 3, col4 = (idx & 7) << 2;
            int gk = k0 + col4;
            int r = bm + row;
            float4 v = *reinterpret_cast<const float4*>(&cdata[(size_t)r*256 + 128 + gk]);
            float4 m = *reinterpret_cast<const float4*>(&statc[256 + gk]);
            float4 o = *reinterpret_cast<const float4*>(&cls[(size_t)r*128 + gk]);
            v.x = (v.x - m.x)*scale*0.25f + 0.1f*o.x;
            v.y = (v.y - m.y)*scale*0.25f + 0.1f*o.y;
            v.z = (v.z - m.z)*scale*0.25f + 0.1f*o.z;
            v.w = (v.w - m.w)*scale*0.25f + 0.1f*o.w;
            *reinterpret_cast<float4*>(&cls[(size_t)r*128 + gk]) = v;
            uint2 h4 = pack_h4(v.x, v.y, v.z, v.w);
            *reinterpret_cast<uint2*>(&clscat[(size_t)r*136 + gk]) = h4;
            *reinterpret_cast<uint2*>(&cmin16[(size_t)r*384 + gk]) = h4;
            aReg[i] = v;
        }
    };
    auto cpB = [&](int c){
        const int k0 = c << 5;
        const uint32_t bb = sbase + B0 + (uint32_t)(c % 3)*PLANE;
        int row = t >> 2, q = t & 3;
        int gk = k0 + q*8;
        cp16ca(bb + (uint32_t)(row*LDH + q*8)*2, Bg + (size_t)row*K + gk, true);
    };
    auto storeA = [&](int s){
        char* sc = smem + A0 + s*PLANE;
        #pragma unroll
        for (int i = 0; i < 2; i++) {
            int idx = t + i*512;
            int row = idx >> 3, col4 = (idx & 7) << 2;
            uint2 pk = pack_h4(aReg[i].x, aReg[i].y, aReg[i].z, aReg[i].w);
            *reinterpret_cast<uint2*>(sc + (row*LDH + col4)*2) = pk;
        }
    };
    auto compute = [&](int c){
        const uint32_t sa = sbase + A0 + (uint32_t)(c & 1)*PLANE;
        const uint32_t sb = sbase + B0 + (uint32_t)(c % 3)*PLANE;
        const int grp = lane >> 3, r = lane & 7;
        #pragma unroll
        for (int ks = 0; ks < 32; ks += 16) {
            uint32_t aH[2][4], bX[4][2];
            #pragma unroll
            for (int mt = 0; mt < 2; mt++) {
                int arow = warp_m*32 + mt*16 + (grp & 1)*8 + r;
                int acol = ks + (grp >> 1)*8;
                ldsm4(aH[mt], sa + (uint32_t)(arow*LDH + acol)*2);
            }
            #pragma unroll
            for (int p = 0; p < 2; p++) {
                int brow = warp_n*32 + p*16 + (grp >> 1)*8 + r;
                int bcol = ks + (grp & 1)*8;
                uint32_t tmp[4];
                ldsm4(tmp, sb + (uint32_t)(brow*LDH + bcol)*2);
                bX[2*p][0]=tmp[0]; bX[2*p][1]=tmp[1]; bX[2*p+1][0]=tmp[2]; bX[2*p+1][1]=tmp[3];
            }
            #pragma unroll
            for (int mt = 0; mt < 2; mt++)
                #pragma unroll
                for (int nt = 0; nt < 4; nt++)
                    mma_f16(acc[mt][nt], aH[mt], bX[nt]);
        }
    };

    loadA(0);
    cpB(0);
    CP_COMMIT();
    storeA(0);
    loadA(1); cpB(1);
    CP_COMMIT();
    CP_WAIT1();
    __syncthreads();

    for (int c = 0; c < nch; c++) {
        compute(c);
        if (c+1 < nch) storeA((c+1) & 1);
        if (c+2 < nch) cpB(c+2);
        CP_COMMIT();
        if (c+2 < nch) loadA(c+2);
        CP_WAIT1();
        __syncthreads();
    }

    float* red = reinterpret_cast<float*>(smem);
    if (t < 128) red[t] = 0.f;
    __syncthreads();
    #pragma unroll
    for (int mt = 0; mt < 2; mt++) {
        int rl = warp_m*32 + mt*16 + (lane >> 2);
        float p0 = 0.f, p1 = 0.f;
        #pragma unroll
        for (int nt = 0; nt < 4; nt++) {
            int col = warp_n*32 + nt*8 + (lane & 3)*2;
            float2 bv = *reinterpret_cast<const float2*>(&bias[col]);
            float wa = __ldg(&w1[col]), wb = __ldg(&w1[col+1]);
            float v0 = fmaxf(acc[mt][nt][0] + bv.x, 0.f);
            float v1 = fmaxf(acc[mt][nt][1] + bv.y, 0.f);
            float v2 = fmaxf(acc[mt][nt][2] + bv.x, 0.f);
            float v3 = fmaxf(acc[mt][nt][3] + bv.y, 0.f);
            p0 += v0*wa + v1*wb;
            p1 += v2*wa + v3*wb;
        }
        atomicAdd(&red[rl], p0);
        atomicAdd(&red[rl+8], p1);
    }
    __syncthreads();
    if (t < 128) {
        float x = red[t] + __ldg(&b1[0]);
        int row = bm + t;
        out[(size_t)round*NC + row] = sigm(x);
        out[(size_t)4*NC + (size_t)round*NC + row] = softplusf(x);
    }
}

// ---------------- setup kernels ----------------
__global__ void k_init(float* p, __half* clscat, __half* varscat, __half* cmin16){
    size_t i = (size_t)blockIdx.x*blockDim.x + threadIdx.x;
    size_t n = (size_t)(NV+NC)*128;
    if (i < n) {
        p[i] = 1.f;
        __half one = __float2half(1.f);
        if (i < (size_t)NV*128) {
            varscat[(i>>7)*136 + (i&127)] = one;
        } else {
            size_t j = i - (size_t)NV*128;
            size_t row = j >> 7, col = j & 127;
            clscat[row*136 + col] = one;
            cmin16[row*384 + col] = one;
        }
    }
    if (i < NL) g_deg[i] = 0;
    if (i < 256) { g_ws[O_STATC + i] = 0.f; g_ws[O_STATV + i] = 0.f; }
}
__global__ void k_count_csr(const int* __restrict__ lit, const int* __restrict__ cls){
    int e = blockIdx.x*blockDim.x + threadIdx.x;
    if (e >= NE) return;
    int l = lit[e];
    int pos = atomicAdd(&g_deg[l], 1);
    if (pos < CSR_W) g_csr[(size_t)l*CSR_W + pos] = cls[e];
}
struct WSrc { const float* w[10]; };
__global__ void k_weights_wsplit(WSrc ws, __half* __restrict__ w16,
                                 const float* __restrict__ nv0, const float* __restrict__ nc0,
                                 __half* __restrict__ clscat, __half* __restrict__ varscat){
    const int offs[11] = {0, 17408, 33792, 51200, 67584, 165888, 231424,
                          362496, 428032, 460800, 477184};
    const int Ks[10]  = {132,128,132,128,384,256,512,256,256,128};
    const int KPs[10] = {136,128,136,128,384,256,512,256,256,128};
    const int Ns[10]  = {128,128,128,128,256,256,256,256,128,128};
    int idx = blockIdx.x*blockDim.x + threadIdx.x;
    if (idx < NL) g_ws[O_DEGW + idx] = rsqrtf(fmaxf((float)g_deg[idx], 1.f));
    if (idx < NV) g_ws[O_VDEGW + idx] = 4.f*rsqrtf(fmaxf((float)(g_deg[idx] + g_deg[idx+NV]), 1.f));
    if (idx < NC) {
        float4 z = *reinterpret_cast<const float4*>(&nc0[(size_t)idx*4]);
        uint2 h = pack_h4(z.x, z.y, z.z, z.w);
        *reinterpret_cast<uint4*>(&clscat[(size_t)idx*136 + 128]) = make_uint4(h.x, h.y, 0u, 0u);
    }
    if (idx < NV) {
        float4 z = *reinterpret_cast<const float4*>(&nv0[(size_t)idx*4]);
        uint2 h = pack_h4(z.x, z.y, z.z, z.w);
        *reinterpret_cast<uint4*>(&varscat[(size_t)idx*136 + 128]) = make_uint4(h.x, h.y, 0u, 0u);
    }
    if (idx >= offs[10]) return;
    int seg = 0;
    #pragma unroll
    for (int s = 1; s < 10; s++) if (idx >= offs[s]) seg = s;
    int local = idx - offs[seg];
    int K = Ks[seg], KP = KPs[seg], N = Ns[seg];
    int n = local / KP, k = local % KP;
    float v = (k < K) ? ws.w[seg][(size_t)k*N + n] : 0.f;
    w16[idx] = __float2half_rn(v);
}

// ---------------- per-round small kernels ----------------
__global__ void k_noise16(const float* __restrict__ nv, const float* __restrict__ nc,
                          __half* __restrict__ clscat, __half* __restrict__ varscat){
    int r = blockIdx.x*blockDim.x + threadIdx.x;
    if (r < NC) {
        float4 z = *reinterpret_cast<const float4*>(&nc[(size_t)r*4]);
        uint2 h = pack_h4(z.x, z.y, z.z, z.w);
        *reinterpret_cast<uint4*>(&clscat[(size_t)r*136 + 128]) = make_uint4(h.x, h.y, 0u, 0u);
    }
    if (r < NV) {
        float4 z = *reinterpret_cast<const float4*>(&nv[(size_t)r*4]);
        uint2 h = pack_h4(z.x, z.y, z.z, z.w);
        *reinterpret_cast<uint4*>(&varscat[(size_t)r*136 + 128]) = make_uint4(h.x, h.y, 0u, 0u);
    }
}
__global__ void k_csum_loss(const int* __restrict__ lit, const int* __restrict__ cls,
                            const float* __restrict__ sp, __half* __restrict__ cmin16){
    const int warp = threadIdx.x >> 5, lane = threadIdx.x & 31;
    const int c = blockIdx.x*4 + warp;
    int s01 = 0;
    if (lane < 2) {
        int key = c + lane;
        int lo = 0, hi = NE;
        while (lo < hi) { int mid = (lo+hi) >> 1; if (cls[mid] < key) lo = mid+1; else hi = mid; }
        s01 = lo;
    }
    int s0 = __shfl_sync(0xffffffffu, s01, 0);
    int s1 = __shfl_sync(0xffffffffu, s01, 1);
    int f4 = lane << 2;
    float4 csum = make_float4(0.f,0.f,0.f,0.f);
    for (int e = s0; e < s1; e++) {
        int l = __ldg(&lit[e]);
        float4 v = *reinterpret_cast<const float4*>(&sp[(size_t)l*128 + f4]);
        csum.x += v.x; csum.y += v.y; csum.z += v.z; csum.w += v.w;
    }
    size_t i = (size_t)c*128 + f4;
    float4 cq = *reinterpret_cast<const float4*>(&g_ws[O_CQ + i]);
    float4 lo4, cg4;
    float sg;
    sg = fsigm(cq.x); lo4.x = __expf(-csum.x)*sg; cg4.x = lo4.x*(1.f-sg)*INV_M;
    sg = fsigm(cq.y); lo4.y = __expf(-csum.y)*sg; cg4.y = lo4.y*(1.f-sg)*INV_M;
    sg = fsigm(cq.z); lo4.z = __expf(-csum.z)*sg; cg4.z = lo4.z*(1.f-sg)*INV_M;
    sg = fsigm(cq.w); lo4.w = __expf(-csum.w)*sg; cg4.w = lo4.w*(1.f-sg)*INV_M;
    *reinterpret_cast<float4*>(&g_ws[O_LOSS + i]) = lo4;
    size_t b = (size_t)c*384;
    *reinterpret_cast<uint2*>(&cmin16[b + 128 + f4]) =
        pack_h4(4.f*lo4.x, 4.f*lo4.y, 4.f*lo4.z, 4.f*lo4.w);
    *reinterpret_cast<uint2*>(&cmin16[b + 256 + f4]) =
        pack_h4(cg4.x, cg4.y, cg4.z, cg4.w);
}
__global__ void k_unit_build(const float* __restrict__ loss, const float* __restrict__ cdata,
                             const float* __restrict__ vq, const float* __restrict__ vars,
                             __half* __restrict__ unit16){
    const int warp = threadIdx.x >> 5, lane = threadIdx.x & 31;
    const int v = blockIdx.x*4 + warp;
    const int f4 = lane << 2;
    int dp = g_deg[v];       if (dp > CSR_W) dp = CSR_W;
    int dn = g_deg[v + NV];  if (dn > CSR_W) dn = CSR_W;
    float4 dlp = make_float4(0,0,0,0), vlp = dlp, dln = dlp, vln = dlp;
    for (int j = 0; j < dp; j++) {
        int c = g_csr[(size_t)v*CSR_W + j];
        float4 a = *reinterpret_cast<const float4*>(&loss[(size_t)c*128 + f4]);
        float4 b = *reinterpret_cast<const float4*>(&cdata[(size_t)c*256 + f4]);
        dlp.x+=a.x; dlp.y+=a.y; dlp.z+=a.z; dlp.w+=a.w;
        vlp.x+=b.x; vlp.y+=b.y; vlp.z+=b.z; vlp.w+=b.w;
    }
    for (int j = 0; j < dn; j++) {
        int c = g_csr[(size_t)(v+NV)*CSR_W + j];
        float4 a = *reinterpret_cast<const float4*>(&loss[(size_t)c*128 + f4]);
        float4 b = *reinterpret_cast<const float4*>(&cdata[(size_t)c*256 + f4]);
        dln.x+=a.x; dln.y+=a.y; dln.z+=a.z; dln.w+=a.w;
        vln.x+=b.x; vln.y+=b.y; vln.z+=b.z; vln.w+=b.w;
    }
    float4 q  = *reinterpret_cast<const float4*>(&vq[(size_t)v*128 + f4]);
    float4 va = *reinterpret_cast<const float4*>(&vars[(size_t)v*128 + f4]);
    float wv = g_ws[O_VDEGW + v];
    float wp = g_ws[O_DEGW + v];
    float wn = g_ws[O_DEGW + NV + v];
    float sp;
    float4 g;
    sp = fsigm(q.x); g.x = -INV_M*(dlp.x*sp - dln.x*(1.f-sp))*wv;
    sp = fsigm(q.y); g.y = -INV_M*(dlp.y*sp - dln.y*(1.f-sp))*wv;
    sp = fsigm(q.z); g.z = -INV_M*(dlp.z*sp - dln.z*(1.f-sp))*wv;
    sp = fsigm(q.w); g.w = -INV_M*(dlp.w*sp - dln.w*(1.f-sp))*wv;
    size_t b = (size_t)v*512;
    *reinterpret_cast<uint2*>(&unit16[b + f4])        = pack_h4(g.x, g.y, g.z, g.w);
    *reinterpret_cast<uint2*>(&unit16[b + 128 + f4])  = pack_h4(va.x, va.y, va.z, va.w);
    *reinterpret_cast<uint2*>(&unit16[b + 256 + f4])  = pack_h4(vlp.x*wp, vlp.y*wp, vlp.z*wp, vlp.w*wp);
    *reinterpret_cast<uint2*>(&unit16[b + 384 + f4])  = pack_h4(vln.x*wn, vln.y*wn, vln.z*wn, vln.w*wn);
}
__global__ void k_pn_scale(float n, float* stat){
    int f = threadIdx.x;
    float mean = stat[f] / n;
    float var  = stat[128 + f] / n - mean*mean;
    __shared__ float sh[128];
    sh[f] = var; __syncthreads();
    for (int s = 64; s > 0; s >>= 1) { if (f < s) sh[f] += sh[f+s]; __syncthreads(); }
    stat[256 + f] = mean;
    if (f == 0) stat[384] = rsqrtf(sh[0]*(1.f/128.f) + 1e-6f);
    stat[f] = 0.f;
    stat[128 + f] = 0.f;
}
__global__ void k_pn_apply(const float* __restrict__ x, const float* __restrict__ stat,
                           float* __restrict__ dst, __half* __restrict__ varscat){
    int r = blockIdx.x, f = threadIdx.x;
    float v = (x[(size_t)r*128 + f] - stat[256 + f]) * stat[384];
    size_t i = (size_t)r*128 + f;
    float o = v*0.25f + 0.1f*dst[i];
    dst[i] = o;
    varscat[(size_t)r*136 + f] = __float2half_rn(o);
}

// ---------------- host ----------------
template<int MT, int STATS, int CH, int SPE>
static void mmgemm(const __half* A16, const __half* Bg1, const __half* Bg2,
                   const float* b1, const float* b2, void* C,
                   int M, int KP, int Ntot, int relu, int rowSplit,
                   float* statp = nullptr, float* spbuf = nullptr){
    constexpr int SMEM = 4*(MT*40*2) + 4*10240;
    cudaFuncSetAttribute(k_mma64<MT,STATS,CH,SPE>,
                         cudaFuncAttributeMaxDynamicSharedMemorySize, SMEM);
    dim3 grid(Ntot/128, M/MT);
    k_mma64<MT,STATS,CH,SPE><<<grid, 256, SMEM>>>(A16, Bg1, Bg2, b1, b2, C,
                                                  KP, Ntot, relu, rowSplit, statp, spbuf);
}

extern "C" void kernel_launch(void* const* d_in, const int* in_sizes, int n_in,
                              void* d_out, int out_size)
{
    (void)in_sizes; (void)n_in; (void)out_size;
    const int*   edge_lit    = (const int*)d_in[0];
    const int*   edge_clause = (const int*)d_in[1];
    const float* noise_v = (const float*)d_in[2];
    const float* noise_c = (const float*)d_in[3];
    const float* vq_w0 = (const float*)d_in[4];  const float* vq_b0 = (const float*)d_in[5];
    const float* vq_w1 = (const float*)d_in[6];  const float* vq_b1 = (const float*)d_in[7];
    const float* cq_w0 = (const float*)d_in[8];  const float* cq_b0 = (const float*)d_in[9];
    const float* cq_w1 = (const float*)d_in[10]; const float* cq_b1 = (const float*)d_in[11];
    const float* cm_w0 = (const float*)d_in[12]; const float* cm_b0 = (const float*)d_in[13];
    const float* cm_w1 = (const float*)d_in[14]; const float* cm_b1 = (const float*)d_in[15];
    const float* ug_w0 = (const float*)d_in[16]; const float* ug_b0 = (const float*)d_in[17];
    const float* ug_w1 = (const float*)d_in[18]; const float* ug_b1 = (const float*)d_in[19];
    const float* ug_w2 = (const float*)d_in[20]; const float* ug_b2 = (const float*)d_in[21];
    const float* co_w0 = (const float*)d_in[22]; const float* co_b0 = (const float*)d_in[23];
    const float* co_w1 = (const float*)d_in[24]; const float* co_b1 = (const float*)d_in[25];
    float* out = (float*)d_out;

    float* ws; cudaGetSymbolAddress((void**)&ws, g_ws);
    __half* w16   = reinterpret_cast<__half*>(ws + O_WT);
    __half* h16   = reinterpret_cast<__half*>(ws + O_H16);
    __half* clscat  = h16 + H_CLSCAT;
    __half* varscat = h16 + H_VARSCAT;
    __half* cmin16  = h16 + H_CMIN;
    __half* unit16  = h16 + H_UNIT;
    __half* h16a    = h16 + H_A;
    __half* h16b    = h16 + H_B;
    float* statc = ws + O_STATC;
    float* statv = ws + O_STATV;
    float* sp    = ws + O_SP;

    cudaFuncSetAttribute(k_co0, cudaFuncAttributeMaxDynamicSharedMemorySize, CO_SMEM);

    {
        size_t n = (size_t)(NV+NC)*128;
        k_init<<<(unsigned)((n+255)/256), 256>>>(ws + O_VARS, clscat, varscat, cmin16);
    }
    k_count_csr<<<(NE+255)/256, 256>>>(edge_lit, edge_clause);
    {
        WSrc s;
        s.w[0]=vq_w0; s.w[1]=vq_w1; s.w[2]=cq_w0; s.w[3]=cq_w1; s.w[4]=cm_w0;
        s.w[5]=cm_w1; s.w[6]=ug_w0; s.w[7]=ug_w1; s.w[8]=ug_w2; s.w[9]=co_w0;
        k_weights_wsplit<<<(OW_END+255)/256, 256>>>(s, w16, noise_v, noise_c,
                                                    clscat, varscat);
    }

    for (int r = 0; r < 4; r++) {
        // merged cq0+vq0 and cq1+vq1 (MT=128)
        mmgemm<128,0,1,0>(clscat, w16+OW_cq0, w16+OW_vq0, cq_b0, vq_b0, h16a,
                          NC+NV, 136, 128, 1, NC);
        mmgemm<128,0,0,1>(h16a, w16+OW_cq1, w16+OW_vq1, cq_b1, vq_b1, ws+O_CQ,
                          NC+NV, 128, 128, 0, NC, nullptr, sp);

        k_csum_loss<<<NC/4, 128>>>(edge_lit, edge_clause, sp, cmin16);

        mmgemm<128,0,1,0>(cmin16, w16+OW_cm0, w16+OW_cm0, cm_b0, cm_b0, h16a,
                          NC, 384, 256, 1, NC);
        mmgemm<128,1,0,0>(h16a, w16+OW_cm1, w16+OW_cm1, cm_b1, cm_b1, ws+O_CDATA,
                          NC, 256, 256, 0, NC, statc);

        k_unit_build<<<NV/4, 128>>>(ws+O_LOSS, ws+O_CDATA, ws+O_VQ, ws+O_VARS, unit16);
        k_pn_scale<<<1, 128>>>((float)NC, statc);

        // ug chain with MT=64 (better wave shape for M=NV)
        mmgemm<64,0,1,0>(unit16, w16+OW_ug0, w16+OW_ug0, ug_b0, ug_b0, h16a,
                         NV, 512, 256, 1, NV);
        mmgemm<64,0,1,0>(h16a, w16+OW_ug1, w16+OW_ug1, ug_b1, ug_b1, h16b,
                         NV, 256, 256, 1, NV);
        mmgemm<64,2,0,0>(h16b, w16+OW_ug2, w16+OW_ug2, ug_b2, ug_b2, ws+O_VOUT,
                         NV, 256, 128, 0, NV, statv);

        k_pn_scale<<<1, 128>>>((float)NV, statv);
        k_pn_apply<<<NV, 128>>>(ws+O_VOUT, statv, ws+O_VARS, varscat);

        k_co0<<<dim3(1, NC/128), 512, CO_SMEM>>>(ws+O_CDATA, ws+O_CLS, statc,
                                                 w16+OW_co0, co_b0, out, r, co_w1, co_b1,
                                                 clscat, cmin16);

        if (r < 3) {
            k_noise16<<<(NC+255)/256, 256>>>(noise_v + (size_t)(r+1)*NV*4,
                                             noise_c + (size_t)(r+1)*NC*4,
                                             clscat, varscat);
        }
    }
}

// round 17
// speedup vs baseline: 1.0246x; 1.0246x over previous
#include <cuda_runtime.h>
#include <cuda_fp16.h>
#include <math.h>
#include <stdint.h>

#define NV 24576
#define NC 98304
#define NE 294912
#define NL 49152
#define INV_M (1.0f/12582912.0f)
#define CSR_W 40

// ---------------- workspace layout (floats) ----------------
static constexpr size_t O_VARS   = 0;
static constexpr size_t O_CLS    = O_VARS  + (size_t)NV*128;
static constexpr size_t O_CQ     = O_CLS   + (size_t)NC*128;
static constexpr size_t O_VQ     = O_CQ    + (size_t)NC*128;
static constexpr size_t O_LOSS   = O_VQ    + (size_t)NV*128;
static constexpr size_t O_CDATA  = O_LOSS  + (size_t)NC*128;   // NC x 256
static constexpr size_t O_VOUT   = O_CDATA + (size_t)NC*256;   // NV x 128
static constexpr size_t O_SP     = O_VOUT  + (size_t)NV*128;   // NL x 128
static constexpr size_t O_DEGW   = O_SP    + (size_t)NL*128;   // NL
static constexpr size_t O_VDEGW  = O_DEGW  + NL;               // NV
static constexpr size_t O_STATC  = O_VDEGW + NV;               // 512
static constexpr size_t O_STATV  = O_STATC + 512;              // 512
static constexpr size_t O_WT     = O_STATV + 512;              // fp16 weights
static constexpr size_t O_H16    = O_WT + 240000;              // fp16 area base

// half offsets within H16 area
static constexpr size_t H_CLSCAT  = 0;                              // NC x 136
static constexpr size_t H_VARSCAT = H_CLSCAT  + (size_t)NC*136;     // NV x 136
static constexpr size_t H_CMIN    = H_VARSCAT + (size_t)NV*136;     // NC x 384
static constexpr size_t H_UNIT    = H_CMIN    + (size_t)NC*384;     // NV x 512
static constexpr size_t H_A       = H_UNIT    + (size_t)NV*512;     // NC x 256
static constexpr size_t H_B       = H_A       + (size_t)NC*256;     // NV x 256
static constexpr size_t H_END     = H_B       + (size_t)NV*256;
static constexpr size_t WS_TOTAL  = O_H16 + (H_END + 1)/2 + 64;

static constexpr size_t OW_vq0 = 0;
static constexpr size_t OW_vq1 = 17408;
static constexpr size_t OW_cq0 = 33792;
static constexpr size_t OW_cq1 = 51200;
static constexpr size_t OW_cm0 = 67584;
static constexpr size_t OW_cm1 = 165888;
static constexpr size_t OW_ug0 = 231424;
static constexpr size_t OW_ug1 = 362496;
static constexpr size_t OW_ug2 = 428032;
static constexpr size_t OW_co0 = 460800;
static constexpr int    OW_END = 477184;

__device__ float g_ws[WS_TOTAL];
__device__ int   g_deg[NL];
__device__ int   g_csr[(size_t)NL * CSR_W];

// ---------------- PTX helpers ----------------
__device__ __forceinline__ uint32_t smem_u32(const void* p){
    uint32_t a;
    asm("{ .reg .u64 t; cvta.to.shared.u64 t, %1; cvt.u32.u64 %0, t; }" : "=r"(a) : "l"(p));
    return a;
}
__device__ __forceinline__ void ldsm4(uint32_t* r, uint32_t addr){
    asm volatile("ldmatrix.sync.aligned.m8n8.x4.shared.b16 {%0,%1,%2,%3}, [%4];"
        : "=r"(r[0]), "=r"(r[1]), "=r"(r[2]), "=r"(r[3]) : "r"(addr));
}
__device__ __forceinline__ void mma_f16(float* c, const uint32_t* a, const uint32_t* b){
    asm volatile("mma.sync.aligned.m16n8k16.row.col.f32.f16.f16.f32 "
        "{%0,%1,%2,%3}, {%4,%5,%6,%7}, {%8,%9}, {%0,%1,%2,%3};"
        : "+f"(c[0]), "+f"(c[1]), "+f"(c[2]), "+f"(c[3])
        : "r"(a[0]), "r"(a[1]), "r"(a[2]), "r"(a[3]), "r"(b[0]), "r"(b[1]));
}
__device__ __forceinline__ void cp16(uint32_t dst, const void* src, bool pred){
    int sz = pred ? 16 : 0;
    asm volatile("cp.async.cg.shared.global [%0], [%1], 16, %2;"
                 :: "r"(dst), "l"(src), "r"(sz));
}
#define CP_COMMIT() asm volatile("cp.async.commit_group;" ::: "memory")
#define CP_WAIT2()  asm volatile("cp.async.wait_group 2;" ::: "memory")
#define CP_WAIT1()  asm volatile("cp.async.wait_group 1;" ::: "memory")

__device__ __forceinline__ float sigm(float x){ return 1.f/(1.f+expf(-x)); }
__device__ __forceinline__ float softplusf(float x){ return fmaxf(x,0.f)+log1pf(expf(-fabsf(x))); }
__device__ __forceinline__ float fsigm(float x){ return __fdividef(1.f, 1.f+__expf(-x)); }
__device__ __forceinline__ float fsoftplus(float x){ return fmaxf(x,0.f)+__logf(1.f+__expf(-fabsf(x))); }

__device__ __forceinline__ uint2 pack_h4(float a, float b, float c, float d){
    __half2 h0 = __floats2half2_rn(a, b);
    __half2 h1 = __floats2half2_rn(c, d);
    uint2 r;
    r.x = *reinterpret_cast<uint32_t*>(&h0);
    r.y = *reinterpret_cast<uint32_t*>(&h1);
    return r;
}

// ---------------- unified fp16 A16 GEMM, tile 128x128, early-prefetch depth-3 ----------------
// 256 thr, 2 CTAs/SM. Dual weight sets selected by bm >= rowSplit.
static constexpr int G64_SMEM = 81920;   // A 4x10240 + B 4x10240

template<int STATS, int CH, int SPE>
__global__ void __launch_bounds__(256, 2)
k_mma64(const __half* __restrict__ A16,
        const __half* __restrict__ Bg1, const __half* __restrict__ Bg2,
        const float* __restrict__ bias1, const float* __restrict__ bias2,
        void* __restrict__ Cv, int KP, int Ntot, int relu, int rowSplit,
        float* __restrict__ statp, float* __restrict__ spbuf)
{
    extern __shared__ __align__(16) char smem[];
    const uint32_t sbase = smem_u32(smem);
    const int t = threadIdx.x;
    const int lane = t & 31, wid = t >> 5;
    const int warp_m = wid & 3;        // 4 x 32 rows
    const int warp_n = wid >> 2;       // 2 x 64 cols
    const int bm = blockIdx.y * 128, bn = blockIdx.x * 128;
    const bool part2 = (bm >= rowSplit);
    const __half* Bg  = part2 ? Bg2 : Bg1;
    const float* bias = part2 ? bias2 : bias1;

    constexpr int LDH = 40, APLANE = 10240, BPLANE = 10240;
    constexpr int A0 = 0, B0 = 40960;

    float acc[2][8][4];
    #pragma unroll
    for (int i=0;i<2;i++)
        #pragma unroll
        for(int j=0;j<8;j++)
            #pragma unroll
            for(int q=0;q<4;q++) acc[i][j][q]=0.f;

    const int nch = (KP + 31) >> 5;

    auto cpAB = [&](int c){
        const int k0 = c << 5;
        const uint32_t ab = sbase + A0 + (uint32_t)(c & 3)*APLANE;
        const uint32_t bb = sbase + B0 + (uint32_t)(c & 3)*BPLANE;
        #pragma unroll
        for (int i = 0; i < 2; i++) {
            int idx = t + i*256;
            int row = idx >> 2, q = idx & 3;
            int gk = k0 + q*8;
            bool ok = (gk + 8 <= KP);
            size_t aoff = ok ? ((size_t)(bm+row)*KP + gk) : 0;
            size_t boff = ok ? ((size_t)(bn+row)*KP + gk) : 0;
            uint32_t so = (uint32_t)(row*LDH + q*8)*2;
            cp16(ab + so, A16 + aoff, ok);
            cp16(bb + so, Bg + boff, ok);
        }
    };
    auto compute = [&](int c){
        const uint32_t sa = sbase + A0 + (uint32_t)(c & 3)*APLANE;
        const uint32_t sb = sbase + B0 + (uint32_t)(c & 3)*BPLANE;
        const int grp = lane >> 3, r = lane & 7;
        #pragma unroll
        for (int ks = 0; ks < 32; ks += 16) {
            uint32_t aH[2][4], bX[8][2];
            #pragma unroll
            for (int mt = 0; mt < 2; mt++) {
                int arow = warp_m*32 + mt*16 + (grp & 1)*8 + r;
                int acol = ks + (grp >> 1)*8;
                ldsm4(aH[mt], sa + (uint32_t)(arow*LDH + acol)*2);
            }
            #pragma unroll
            for (int p = 0; p < 4; p++) {
                int brow = warp_n*64 + p*16 + (grp >> 1)*8 + r;
                int bcol = ks + (grp & 1)*8;
                uint32_t tmp[4];
                ldsm4(tmp, sb + (uint32_t)(brow*LDH + bcol)*2);
                bX[2*p][0]=tmp[0]; bX[2*p][1]=tmp[1]; bX[2*p+1][0]=tmp[2]; bX[2*p+1][1]=tmp[3];
            }
            #pragma unroll
            for (int mt = 0; mt < 2; mt++)
                #pragma unroll
                for (int nt = 0; nt < 8; nt++)
                    mma_f16(acc[mt][nt], aH[mt], bX[nt]);
        }
    };

    cpAB(0);
    CP_COMMIT();
    if (nch > 1) cpAB(1);
    CP_COMMIT();
    if (nch > 2) cpAB(2);
    CP_COMMIT();

    for (int c = 0; c < nch; c++) {
        CP_WAIT2();
        __syncthreads();
        if (c+3 < nch) cpAB(c+3);
        CP_COMMIT();
        compute(c);
    }

    // ---- C store (+SPE) ----
    #pragma unroll
    for (int mt = 0; mt < 2; mt++) {
        int row0 = bm + warp_m*32 + mt*16 + (lane >> 2);
        #pragma unroll
        for (int nt = 0; nt < 8; nt++) {
            int col = bn + warp_n*64 + nt*8 + (lane & 3)*2;
            float2 bv = *reinterpret_cast<const float2*>(&bias[col - bn]);
            float v0 = acc[mt][nt][0] + bv.x, v1 = acc[mt][nt][1] + bv.y;
            float v2 = acc[mt][nt][2] + bv.x, v3 = acc[mt][nt][3] + bv.y;
            if (relu) { v0=fmaxf(v0,0.f); v1=fmaxf(v1,0.f); v2=fmaxf(v2,0.f); v3=fmaxf(v3,0.f); }
            if (CH) {
                __half* C16 = reinterpret_cast<__half*>(Cv);
                __half2 h01 = __floats2half2_rn(v0, v1);
                __half2 h23 = __floats2half2_rn(v2, v3);
                *reinterpret_cast<__half2*>(&C16[(size_t)row0*Ntot + col])     = h01;
                *reinterpret_cast<__half2*>(&C16[(size_t)(row0+8)*Ntot + col]) = h23;
            } else {
                float* C = reinterpret_cast<float*>(Cv);
                *reinterpret_cast<float2*>(&C[(size_t)row0*Ntot + col])     = make_float2(v0,v1);
                *reinterpret_cast<float2*>(&C[(size_t)(row0+8)*Ntot + col]) = make_float2(v2,v3);
            }
            if (SPE) {
                if (part2) {
                    int rv = row0 - rowSplit;
                    *reinterpret_cast<float2*>(&spbuf[(size_t)rv*128 + col]) =
                        make_float2(fsoftplus(v0), fsoftplus(v1));
                    *reinterpret_cast<float2*>(&spbuf[(size_t)(rv+NV)*128 + col]) =
                        make_float2(fsoftplus(-v0), fsoftplus(-v1));
                    *reinterpret_cast<float2*>(&spbuf[(size_t)(rv+8)*128 + col]) =
                        make_float2(fsoftplus(v2), fsoftplus(v3));
                    *reinterpret_cast<float2*>(&spbuf[(size_t)(rv+8+NV)*128 + col]) =
                        make_float2(fsoftplus(-v2), fsoftplus(-v3));
                }
            }
        }
    }

    if (STATS) {
        bool active = (STATS == 2) || (bn >= 128);
        if (active) {
            __syncthreads();
            float* red = reinterpret_cast<float*>(smem);
            if (t < 256) red[t] = 0.f;
            __syncthreads();
            #pragma unroll
            for (int nt = 0; nt < 8; nt++) {
                int c0 = warp_n*64 + nt*8 + (lane & 3)*2;
                float b0 = __ldg(&bias[c0]), b1 = __ldg(&bias[c0 + 1]);
                float s0=0.f, s1=0.f, q0=0.f, q1=0.f;
                #pragma unroll
                for (int mt = 0; mt < 2; mt++) {
                    float v0 = acc[mt][nt][0] + b0, v1 = acc[mt][nt][1] + b1;
                    float v2 = acc[mt][nt][2] + b0, v3 = acc[mt][nt][3] + b1;
                    s0 += v0 + v2; s1 += v1 + v3;
                    q0 += v0*v0 + v2*v2; q1 += v1*v1 + v3*v3;
                }
                #pragma unroll
                for (int o = 4; o < 32; o <<= 1) {
                    s0 += __shfl_xor_sync(0xffffffffu, s0, o);
                    s1 += __shfl_xor_sync(0xffffffffu, s1, o);
                    q0 += __shfl_xor_sync(0xffffffffu, q0, o);
                    q1 += __shfl_xor_sync(0xffffffffu, q1, o);
                }
                if (lane < 4) {
                    atomicAdd(&red[c0],        s0);
                    atomicAdd(&red[c0+1],      s1);
                    atomicAdd(&red[128+c0],    q0);
                    atomicAdd(&red[128+c0+1],  q1);
                }
            }
            __syncthreads();
            if (t < 128) {
                atomicAdd(&statp[t],       red[t]);
                atomicAdd(&statp[128 + t], red[128 + t]);
            }
        }
    }
}

// ---------------- co0: pn-apply loader (+fp16 state writes) + logits, early prefetch ----
static constexpr int CO_SMEM = 51200;

__global__ void __launch_bounds__(512, 1)
k_co0(const float* __restrict__ cdata, float* __restrict__ cls,
      const float* __restrict__ statc,
      const __half* __restrict__ Bg, const float* __restrict__ bias,
      float* __restrict__ out, int round,
      const float* __restrict__ w1, const float* __restrict__ b1,
      __half* __restrict__ clscat, __half* __restrict__ cmin16)
{
    extern __shared__ __align__(16) char smem[];
    const uint32_t sbase = smem_u32(smem);
    const int t = threadIdx.x;
    const int lane = t & 31, wid = t >> 5;
    const int warp_m = wid & 3, warp_n = wid >> 2;
    const int bm = blockIdx.y * 128;

    constexpr int LDH = 40, PLANE = 10240, A0 = 0, B0 = 20480;
    constexpr int K = 128, nch = 4;

    float acc[2][4][4];
    #pragma unroll
    for (int i=0;i<2;i++)
        #pragma unroll
        for(int j=0;j<4;j++)
            #pragma unroll
            for(int q=0;q<4;q++) acc[i][j][q]=0.f;

    float4 aReg[2];
    const float scale = statc[384];

    auto loadA = [&](int c){
        const int k0 = c << 5;
        #pragma unroll
        for (int i = 0; i < 2; i++) {
            int idx = t + i*512;
            int row = idx >> 3, col4 = (idx & 7) << 2;
            int gk = k0 + col4;
            int r = bm + row;
            float4 v = *reinterpret_cast<const float4*>(&cdata[(size_t)r*256 + 128 + gk]);
            float4 m = *reinterpret_cast<const float4*>(&statc[256 + gk]);
            float4 o = *reinterpret_cast<const float4*>(&cls[(size_t)r*128 + gk]);
            v.x = (v.x - m.x)*scale*0.25f + 0.1f*o.x;
            v.y = (v.y - m.y)*scale*0.25f + 0.1f*o.y;
            v.z = (v.z - m.z)*scale*0.25f + 0.1f*o.z;
            v.w = (v.w - m.w)*scale*0.25f + 0.1f*o.w;
            *reinterpret_cast<float4*>(&cls[(size_t)r*128 + gk]) = v;
            uint2 h4 = pack_h4(v.x, v.y, v.z, v.w);
            *reinterpret_cast<uint2*>(&clscat[(size_t)r*136 + gk]) = h4;
            *reinterpret_cast<uint2*>(&cmin16[(size_t)r*384 + gk]) = h4;
            aReg[i] = v;
        }
    };
    auto cpB = [&](int c){
        const int k0 = c << 5;
        const uint32_t bb = sbase + B0 + (uint32_t)(c % 3)*PLANE;
        int row = t >> 2, q = t & 3;
        int gk = k0 + q*8;
        cp16(bb + (uint32_t)(row*LDH + q*8)*2, Bg + (size_t)row*K + gk, true);
    };
    auto storeA = [&](int s){
        char* sc = smem + A0 + s*PLANE;
        #pragma unroll
        for (int i = 0; i < 2; i++) {
            int idx = t + i*512;
            int row = idx >> 3, col4 = (idx & 7) << 2;
            uint2 pk = pack_h4(aReg[i].x, aReg[i].y, aReg[i].z, aReg[i].w);
            *reinterpret_cast<uint2*>(sc + (row*LDH + col4)*2) = pk;
        }
    };
    auto compute = [&](int c){
        const uint32_t sa = sbase + A0 + (uint32_t)(c & 1)*PLANE;
        const uint32_t sb = sbase + B0 + (uint32_t)(c % 3)*PLANE;
        const int grp = lane >> 3, r = lane & 7;
        #pragma unroll
        for (int ks = 0; ks < 32; ks += 16) {
            uint32_t aH[2][4], bX[4][2];
            #pragma unroll
            for (int mt = 0; mt < 2; mt++) {
                int arow = warp_m*32 + mt*16 + (grp & 1)*8 + r;
                int acol = ks + (grp >> 1)*8;
                ldsm4(aH[mt], sa + (uint32_t)(arow*LDH + acol)*2);
            }
            #pragma unroll
            for (int p = 0; p < 2; p++) {
                int brow = warp_n*32 + p*16 + (grp >> 1)*8 + r;
                int bcol = ks + (grp & 1)*8;
                uint32_t tmp[4];
                ldsm4(tmp, sb + (uint32_t)(brow*LDH + bcol)*2);
                bX[2*p][0]=tmp[0]; bX[2*p][1]=tmp[1]; bX[2*p+1][0]=tmp[2]; bX[2*p+1][1]=tmp[3];
            }
            #pragma unroll
            for (int mt = 0; mt < 2; mt++)
                #pragma unroll
                for (int nt = 0; nt < 4; nt++)
                    mma_f16(acc[mt][nt], aH[mt], bX[nt]);
        }
    };

    // prologue: A(0) in smem, A(1) in regs, B(0)/B(1) in flight
    loadA(0);
    cpB(0);
    CP_COMMIT();
    storeA(0);
    loadA(1); cpB(1);
    CP_COMMIT();
    CP_WAIT1();
    __syncthreads();

    // early-prefetch loop: global work for c+2 issued before compute(c)
    for (int c = 0; c < nch; c++) {
        if (c+1 < nch) storeA((c+1) & 1);   // buf (c-1)&1 drained before last sync
        if (c+2 < nch) { loadA(c+2); cpB(c+2); }
        CP_COMMIT();
        compute(c);
        CP_WAIT1();
        __syncthreads();
    }

    float* red = reinterpret_cast<float*>(smem);
    if (t < 128) red[t] = 0.f;
    __syncthreads();
    #pragma unroll
    for (int mt = 0; mt < 2; mt++) {
        int rl = warp_m*32 + mt*16 + (lane >> 2);
        float p0 = 0.f, p1 = 0.f;
        #pragma unroll
        for (int nt = 0; nt < 4; nt++) {
            int col = warp_n*32 + nt*8 + (lane & 3)*2;
            float2 bv = *reinterpret_cast<const float2*>(&bias[col]);
            float wa = __ldg(&w1[col]), wb = __ldg(&w1[col+1]);
            float v0 = fmaxf(acc[mt][nt][0] + bv.x, 0.f);
            float v1 = fmaxf(acc[mt][nt][1] + bv.y, 0.f);
            float v2 = fmaxf(acc[mt][nt][2] + bv.x, 0.f);
            float v3 = fmaxf(acc[mt][nt][3] + bv.y, 0.f);
            p0 += v0*wa + v1*wb;
            p1 += v2*wa + v3*wb;
        }
        atomicAdd(&red[rl], p0);
        atomicAdd(&red[rl+8], p1);
    }
    __syncthreads();
    if (t < 128) {
        float x = red[t] + __ldg(&b1[0]);
        int row = bm + t;
        out[(size_t)round*NC + row] = sigm(x);
        out[(size_t)4*NC + (size_t)round*NC + row] = softplusf(x);
    }
}

// ---------------- setup kernels ----------------
__global__ void k_init(float* p, __half* clscat, __half* varscat, __half* cmin16){
    size_t i = (size_t)blockIdx.x*blockDim.x + threadIdx.x;
    size_t n = (size_t)(NV+NC)*128;
    if (i < n) {
        p[i] = 1.f;
        __half one = __float2half(1.f);
        if (i < (size_t)NV*128) {
            varscat[(i>>7)*136 + (i&127)] = one;
        } else {
            size_t j = i - (size_t)NV*128;
            size_t row = j >> 7, col = j & 127;
            clscat[row*136 + col] = one;
            cmin16[row*384 + col] = one;
        }
    }
    if (i < NL) g_deg[i] = 0;
    if (i < 256) { g_ws[O_STATC + i] = 0.f; g_ws[O_STATV + i] = 0.f; }
}
__global__ void k_count_csr(const int* __restrict__ lit, const int* __restrict__ cls){
    int e = blockIdx.x*blockDim.x + threadIdx.x;
    if (e >= NE) return;
    int l = lit[e];
    int pos = atomicAdd(&g_deg[l], 1);
    if (pos < CSR_W) g_csr[(size_t)l*CSR_W + pos] = cls[e];
}
struct WSrc { const float* w[10]; };
__global__ void k_weights_wsplit(WSrc ws, __half* __restrict__ w16,
                                 const float* __restrict__ nv0, const float* __restrict__ nc0,
                                 __half* __restrict__ clscat, __half* __restrict__ varscat){
    const int offs[11] = {0, 17408, 33792, 51200, 67584, 165888, 231424,
                          362496, 428032, 460800, 477184};
    const int Ks[10]  = {132,128,132,128,384,256,512,256,256,128};
    const int KPs[10] = {136,128,136,128,384,256,512,256,256,128};
    const int Ns[10]  = {128,128,128,128,256,256,256,256,128,128};
    int idx = blockIdx.x*blockDim.x + threadIdx.x;
    if (idx < NL) g_ws[O_DEGW + idx] = rsqrtf(fmaxf((float)g_deg[idx], 1.f));
    if (idx < NV) g_ws[O_VDEGW + idx] = 4.f*rsqrtf(fmaxf((float)(g_deg[idx] + g_deg[idx+NV]), 1.f));
    if (idx < NC) {
        float4 z = *reinterpret_cast<const float4*>(&nc0[(size_t)idx*4]);
        uint2 h = pack_h4(z.x, z.y, z.z, z.w);
        *reinterpret_cast<uint4*>(&clscat[(size_t)idx*136 + 128]) = make_uint4(h.x, h.y, 0u, 0u);
    }
    if (idx < NV) {
        float4 z = *reinterpret_cast<const float4*>(&nv0[(size_t)idx*4]);
        uint2 h = pack_h4(z.x, z.y, z.z, z.w);
        *reinterpret_cast<uint4*>(&varscat[(size_t)idx*136 + 128]) = make_uint4(h.x, h.y, 0u, 0u);
    }
    if (idx >= offs[10]) return;
    int seg = 0;
    #pragma unroll
    for (int s = 1; s < 10; s++) if (idx >= offs[s]) seg = s;
    int local = idx - offs[seg];
    int K = Ks[seg], KP = KPs[seg], N = Ns[seg];
    int n = local / KP, k = local % KP;
    float v = (k < K) ? ws.w[seg][(size_t)k*N + n] : 0.f;
    w16[idx] = __float2half_rn(v);
}

// ---------------- per-round small kernels ----------------
__global__ void k_noise16(const float* __restrict__ nv, const float* __restrict__ nc,
                          __half* __restrict__ clscat, __half* __restrict__ varscat){
    int r = blockIdx.x*blockDim.x + threadIdx.x;
    if (r < NC) {
        float4 z = *reinterpret_cast<const float4*>(&nc[(size_t)r*4]);
        uint2 h = pack_h4(z.x, z.y, z.z, z.w);
        *reinterpret_cast<uint4*>(&clscat[(size_t)r*136 + 128]) = make_uint4(h.x, h.y, 0u, 0u);
    }
    if (r < NV) {
        float4 z = *reinterpret_cast<const float4*>(&nv[(size_t)r*4]);
        uint2 h = pack_h4(z.x, z.y, z.z, z.w);
        *reinterpret_cast<uint4*>(&varscat[(size_t)r*136 + 128]) = make_uint4(h.x, h.y, 0u, 0u);
    }
}
__global__ void k_csum_loss(const int* __restrict__ lit, const int* __restrict__ cls,
                            const float* __restrict__ sp, __half* __restrict__ cmin16){
    const int warp = threadIdx.x >> 5, lane = threadIdx.x & 31;
    const int c = blockIdx.x*4 + warp;
    int s01 = 0;
    if (lane < 2) {
        int key = c + lane;
        int lo = 0, hi = NE;
        while (lo < hi) { int mid = (lo+hi) >> 1; if (cls[mid] < key) lo = mid+1; else hi = mid; }
        s01 = lo;
    }
    int s0 = __shfl_sync(0xffffffffu, s01, 0);
    int s1 = __shfl_sync(0xffffffffu, s01, 1);
    int f4 = lane << 2;
    float4 csum = make_float4(0.f,0.f,0.f,0.f);
    for (int e = s0; e < s1; e++) {
        int l = __ldg(&lit[e]);
        float4 v = *reinterpret_cast<const float4*>(&sp[(size_t)l*128 + f4]);
        csum.x += v.x; csum.y += v.y; csum.z += v.z; csum.w += v.w;
    }
    size_t i = (size_t)c*128 + f4;
    float4 cq = *reinterpret_cast<const float4*>(&g_ws[O_CQ + i]);
    float4 lo4, cg4;
    float sg;
    sg = fsigm(cq.x); lo4.x = __expf(-csum.x)*sg; cg4.x = lo4.x*(1.f-sg)*INV_M;
    sg = fsigm(cq.y); lo4.y = __expf(-csum.y)*sg; cg4.y = lo4.y*(1.f-sg)*INV_M;
    sg = fsigm(cq.z); lo4.z = __expf(-csum.z)*sg; cg4.z = lo4.z*(1.f-sg)*INV_M;
    sg = fsigm(cq.w); lo4.w = __expf(-csum.w)*sg; cg4.w = lo4.w*(1.f-sg)*INV_M;
    *reinterpret_cast<float4*>(&g_ws[O_LOSS + i]) = lo4;
    size_t b = (size_t)c*384;
    *reinterpret_cast<uint2*>(&cmin16[b + 128 + f4]) =
        pack_h4(4.f*lo4.x, 4.f*lo4.y, 4.f*lo4.z, 4.f*lo4.w);
    *reinterpret_cast<uint2*>(&cmin16[b + 256 + f4]) =
        pack_h4(cg4.x, cg4.y, cg4.z, cg4.w);
}
__global__ void k_unit_build(const float* __restrict__ loss, const float* __restrict__ cdata,
                             const float* __restrict__ vq, const float* __restrict__ vars,
                             __half* __restrict__ unit16){
    const int warp = threadIdx.x >> 5, lane = threadIdx.x & 31;
    const int v = blockIdx.x*4 + warp;
    const int f4 = lane << 2;
    int dp = g_deg[v];       if (dp > CSR_W) dp = CSR_W;
    int dn = g_deg[v + NV];  if (dn > CSR_W) dn = CSR_W;
    float4 dlp = make_float4(0,0,0,0), vlp = dlp, dln = dlp, vln = dlp;
    for (int j = 0; j < dp; j++) {
        int c = g_csr[(size_t)v*CSR_W + j];
        float4 a = *reinterpret_cast<const float4*>(&loss[(size_t)c*128 + f4]);
        float4 b = *reinterpret_cast<const float4*>(&cdata[(size_t)c*256 + f4]);
        dlp.x+=a.x; dlp.y+=a.y; dlp.z+=a.z; dlp.w+=a.w;
        vlp.x+=b.x; vlp.y+=b.y; vlp.z+=b.z; vlp.w+=b.w;
    }
    for (int j = 0; j < dn; j++) {
        int c = g_csr[(size_t)(v+NV)*CSR_W + j];
        float4 a = *reinterpret_cast<const float4*>(&loss[(size_t)c*128 + f4]);
        float4 b = *reinterpret_cast<const float4*>(&cdata[(size_t)c*256 + f4]);
        dln.x+=a.x; dln.y+=a.y; dln.z+=a.z; dln.w+=a.w;
        vln.x+=b.x; vln.y+=b.y; vln.z+=b.z; vln.w+=b.w;
    }
    float4 q  = *reinterpret_cast<const float4*>(&vq[(size_t)v*128 + f4]);
    float4 va = *reinterpret_cast<const float4*>(&vars[(size_t)v*128 + f4]);
    float wv = g_ws[O_VDEGW + v];
    float wp = g_ws[O_DEGW + v];
    float wn = g_ws[O_DEGW + NV + v];
    float sp;
    float4 g;
    sp = fsigm(q.x); g.x = -INV_M*(dlp.x*sp - dln.x*(1.f-sp))*wv;
    sp = fsigm(q.y); g.y = -INV_M*(dlp.y*sp - dln.y*(1.f-sp))*wv;
    sp = fsigm(q.z); g.z = -INV_M*(dlp.z*sp - dln.z*(1.f-sp))*wv;
    sp = fsigm(q.w); g.w = -INV_M*(dlp.w*sp - dln.w*(1.f-sp))*wv;
    size_t b = (size_t)v*512;
    *reinterpret_cast<uint2*>(&unit16[b + f4])        = pack_h4(g.x, g.y, g.z, g.w);
    *reinterpret_cast<uint2*>(&unit16[b + 128 + f4])  = pack_h4(va.x, va.y, va.z, va.w);
    *reinterpret_cast<uint2*>(&unit16[b + 256 + f4])  = pack_h4(vlp.x*wp, vlp.y*wp, vlp.z*wp, vlp.w*wp);
    *reinterpret_cast<uint2*>(&unit16[b + 384 + f4])  = pack_h4(vln.x*wn, vln.y*wn, vln.z*wn, vln.w*wn);
}
__global__ void k_pn_scale(float n, float* stat){
    int f = threadIdx.x;
    float mean = stat[f] / n;
    float var  = stat[128 + f] / n - mean*mean;
    __shared__ float sh[128];
    sh[f] = var; __syncthreads();
    for (int s = 64; s > 0; s >>= 1) { if (f < s) sh[f] += sh[f+s]; __syncthreads(); }
    stat[256 + f] = mean;
    if (f == 0) stat[384] = rsqrtf(sh[0]*(1.f/128.f) + 1e-6f);
    stat[f] = 0.f;
    stat[128 + f] = 0.f;
}
__global__ void k_pn_apply(const float* __restrict__ x, const float* __restrict__ stat,
                           float* __restrict__ dst, __half* __restrict__ varscat){
    int r = blockIdx.x, f = threadIdx.x;
    float v = (x[(size_t)r*128 + f] - stat[256 + f]) * stat[384];
    size_t i = (size_t)r*128 + f;
    float o = v*0.25f + 0.1f*dst[i];
    dst[i] = o;
    varscat[(size_t)r*136 + f] = __float2half_rn(o);
}

// ---------------- host ----------------
template<int STATS, int CH, int SPE>
static void mmgemm(const __half* A16, const __half* Bg1, const __half* Bg2,
                   const float* b1, const float* b2, void* C,
                   int M, int KP, int Ntot, int relu, int rowSplit,
                   float* statp = nullptr, float* spbuf = nullptr){
    cudaFuncSetAttribute(k_mma64<STATS,CH,SPE>,
                         cudaFuncAttributeMaxDynamicSharedMemorySize, G64_SMEM);
    dim3 grid(Ntot/128, M/128);
    k_mma64<STATS,CH,SPE><<<grid, 256, G64_SMEM>>>(A16, Bg1, Bg2, b1, b2, C,
                                                   KP, Ntot, relu, rowSplit, statp, spbuf);
}

extern "C" void kernel_launch(void* const* d_in, const int* in_sizes, int n_in,
                              void* d_out, int out_size)
{
    (void)in_sizes; (void)n_in; (void)out_size;
    const int*   edge_lit    = (const int*)d_in[0];
    const int*   edge_clause = (const int*)d_in[1];
    const float* noise_v = (const float*)d_in[2];
    const float* noise_c = (const float*)d_in[3];
    const float* vq_w0 = (const float*)d_in[4];  const float* vq_b0 = (const float*)d_in[5];
    const float* vq_w1 = (const float*)d_in[6];  const float* vq_b1 = (const float*)d_in[7];
    const float* cq_w0 = (const float*)d_in[8];  const float* cq_b0 = (const float*)d_in[9];
    const float* cq_w1 = (const float*)d_in[10]; const float* cq_b1 = (const float*)d_in[11];
    const float* cm_w0 = (const float*)d_in[12]; const float* cm_b0 = (const float*)d_in[13];
    const float* cm_w1 = (const float*)d_in[14]; const float* cm_b1 = (const float*)d_in[15];
    const float* ug_w0 = (const float*)d_in[16]; const float* ug_b0 = (const float*)d_in[17];
    const float* ug_w1 = (const float*)d_in[18]; const float* ug_b1 = (const float*)d_in[19];
    const float* ug_w2 = (const float*)d_in[20]; const float* ug_b2 = (const float*)d_in[21];
    const float* co_w0 = (const float*)d_in[22]; const float* co_b0 = (const float*)d_in[23];
    const float* co_w1 = (const float*)d_in[24]; const float* co_b1 = (const float*)d_in[25];
    float* out = (float*)d_out;

    float* ws; cudaGetSymbolAddress((void**)&ws, g_ws);
    __half* w16   = reinterpret_cast<__half*>(ws + O_WT);
    __half* h16   = reinterpret_cast<__half*>(ws + O_H16);
    __half* clscat  = h16 + H_CLSCAT;
    __half* varscat = h16 + H_VARSCAT;
    __half* cmin16  = h16 + H_CMIN;
    __half* unit16  = h16 + H_UNIT;
    __half* h16a    = h16 + H_A;
    __half* h16b    = h16 + H_B;
    float* statc = ws + O_STATC;
    float* statv = ws + O_STATV;
    float* sp    = ws + O_SP;

    cudaFuncSetAttribute(k_co0, cudaFuncAttributeMaxDynamicSharedMemorySize, CO_SMEM);

    {
        size_t n = (size_t)(NV+NC)*128;
        k_init<<<(unsigned)((n+255)/256), 256>>>(ws + O_VARS, clscat, varscat, cmin16);
    }
    k_count_csr<<<(NE+255)/256, 256>>>(edge_lit, edge_clause);
    {
        WSrc s;
        s.w[0]=vq_w0; s.w[1]=vq_w1; s.w[2]=cq_w0; s.w[3]=cq_w1; s.w[4]=cm_w0;
        s.w[5]=cm_w1; s.w[6]=ug_w0; s.w[7]=ug_w1; s.w[8]=ug_w2; s.w[9]=co_w0;
        k_weights_wsplit<<<(OW_END+255)/256, 256>>>(s, w16, noise_v, noise_c,
                                                    clscat, varscat);
    }

    for (int r = 0; r < 4; r++) {
        mmgemm<0,1,0>(clscat, w16+OW_cq0, w16+OW_vq0, cq_b0, vq_b0, h16a,
                      NC+NV, 136, 128, 1, NC);
        mmgemm<0,0,1>(h16a, w16+OW_cq1, w16+OW_vq1, cq_b1, vq_b1, ws+O_CQ,
                      NC+NV, 128, 128, 0, NC, nullptr, sp);

        k_csum_loss<<<NC/4, 128>>>(edge_lit, edge_clause, sp, cmin16);

        mmgemm<0,1,0>(cmin16, w16+OW_cm0, w16+OW_cm0, cm_b0, cm_b0, h16a,
                      NC, 384, 256, 1, NC);
        mmgemm<1,0,0>(h16a, w16+OW_cm1, w16+OW_cm1, cm_b1, cm_b1, ws+O_CDATA,
                      NC, 256, 256, 0, NC, statc);

        k_unit_build<<<NV/4, 128>>>(ws+O_LOSS, ws+O_CDATA, ws+O_VQ, ws+O_VARS, unit16);
        k_pn_scale<<<1, 128>>>((float)NC, statc);

        mmgemm<0,1,0>(unit16, w16+OW_ug0, w16+OW_ug0, ug_b0, ug_b0, h16a,
                      NV, 512, 256, 1, NV);
        mmgemm<0,1,0>(h16a, w16+OW_ug1, w16+OW_ug1, ug_b1, ug_b1, h16b,
                      NV, 256, 256, 1, NV);
        mmgemm<2,0,0>(h16b, w16+OW_ug2, w16+OW_ug2, ug_b2, ug_b2, ws+O_VOUT,
                      NV, 256, 128, 0, NV, statv);

        k_pn_scale<<<1, 128>>>((float)NV, statv);
        k_pn_apply<<<NV, 128>>>(ws+O_VOUT, statv, ws+O_VARS, varscat);

        k_co0<<<dim3(1, NC/128), 512, CO_SMEM>>>(ws+O_CDATA, ws+O_CLS, statc,
                                                 w16+OW_co0, co_b0, out, r, co_w1, co_b1,
                                                 clscat, cmin16);

        if (r < 3) {
            k_noise16<<<(NC+255)/256, 256>>>(noise_v + (size_t)(r+1)*NV*4,
                                             noise_c + (size_t)(r+1)*NC*4,
                                             clscat, varscat);
        }
    }
}